// round 10
// baseline (speedup 1.0000x reference)
#include <cuda_runtime.h>
#include <cuda_fp16.h>
#include <cstdint>
#include <cstddef>

// Problem constants
#define BB 8
#define NSEQ 4096
#define NN 32768            // BB*NSEQ nodes
#define H 128
#define EDGES 524288
#define RREL 8
#define NLAYERS 2

#define PITCH_W 136         // fp16 elems per W smem row (272B)
#define PITCH_A 40          // fp16 elems per A-chunk smem row (80B; 32 data + 8 pad)

// ---- smem map for proj kernel (fp16 element offsets) ----
#define SW_H   0
#define SW_L   (128 * PITCH_W)                 // 17408
#define SA_OFF (2 * 128 * PITCH_W)             // 34816
#define SA_SZ  (128 * PITCH_A)                 // 5120 per buffer
#define SM_ELEMS (SA_OFF + 2 * SA_SZ)          // 45056 fp16 = 90112 B

// ---- smem map for fused layer kernel ----
#define FA_OFF 0                               // A tile: 128*PITCH_W
#define FW0    (128 * PITCH_W)                 // W buffer 0
#define FW1    (2 * 128 * PITCH_W)             // W buffer 1
#define FSM_ELEMS (3 * 128 * PITCH_W)          // 52224 fp16 = 104448 B

#define NMAT (1 + NLAYERS * (RREL + 1))        // 19 weight matrices
#define SCALE 64.0f
#define INV_SCALE2 (1.0f / 4096.0f)

// ---------------- scratch (static device globals; no allocation) ----------------
__device__ float g_Z[(size_t)NN * H];            // self-GEMM out / agg accumulator (16 MB)
__device__ __half g_Y[(size_t)RREL * NN * H];    // per-relation messages, fp16 (64 MB)
__device__ __half g_Xf[(size_t)NN * H];          // node states, fp16 scaled x64 (8 MB)
__device__ __half g_Wh[(size_t)NMAT * H * H];    // weight hi splits (x64)
__device__ __half g_Wl[(size_t)NMAT * H * H];    // weight lo splits
__device__ float g_deg[NN];

// ---------------- helpers ----------------
__device__ __forceinline__ uint32_t smem_u32(const void* p) {
    uint32_t a;
    asm("{ .reg .u64 t; cvta.to.shared.u64 t, %1; cvt.u32.u64 %0, t; }" : "=r"(a) : "l"(p));
    return a;
}
__device__ __forceinline__ void cp_async16(uint32_t dst, const void* src) {
    asm volatile("cp.async.cg.shared.global [%0], [%1], 16;" :: "r"(dst), "l"(src));
}
__device__ __forceinline__ void cp_commit() {
    asm volatile("cp.async.commit_group;");
}
__device__ __forceinline__ void cp_wait0() {
    asm volatile("cp.async.wait_group 0;");
}
__device__ __forceinline__ void ldm_x4(uint32_t& r0, uint32_t& r1, uint32_t& r2, uint32_t& r3,
                                       uint32_t addr) {
    asm volatile("ldmatrix.sync.aligned.m8n8.x4.shared.b16 {%0,%1,%2,%3}, [%4];"
                 : "=r"(r0), "=r"(r1), "=r"(r2), "=r"(r3) : "r"(addr));
}
__device__ __forceinline__ void mma16816(float* d, const uint32_t* a, uint32_t b0, uint32_t b1) {
    asm volatile(
        "mma.sync.aligned.m16n8k16.row.col.f32.f16.f16.f32 "
        "{%0,%1,%2,%3}, {%4,%5,%6,%7}, {%8,%9}, {%0,%1,%2,%3};"
        : "+f"(d[0]), "+f"(d[1]), "+f"(d[2]), "+f"(d[3])
        : "r"(a[0]), "r"(a[1]), "r"(a[2]), "r"(a[3]), "r"(b0), "r"(b1));
}
__device__ __forceinline__ void split_h16(float v, __half& hi, __half& lo) {
    hi = __float2half(v);
    lo = __float2half(v - __half2float(hi));
}

// ---------------- embed: Xf = fp16(64*(concept_emb[cid]+kind_emb[kid])); zero deg ------
__global__ __launch_bounds__(256) void embed_kernel(const int* __restrict__ cid,
                                                    const int* __restrict__ kid,
                                                    const float* __restrict__ cemb,
                                                    const float* __restrict__ kemb) {
    int t = blockIdx.x * 256 + threadIdx.x;        // one float4 per thread
    if (t < NN) g_deg[t] = 0.0f;
    int node = t >> 5;
    int q = t & 31;
    int c = __ldg(cid + node);
    int k = __ldg(kid + node);
    float4 a = __ldg(((const float4*)(cemb + (size_t)c * H)) + q);
    float4 b = __ldg(((const float4*)(kemb + (size_t)k * H)) + q);
    __half h[4];
    h[0] = __float2half(SCALE * (a.x + b.x));
    h[1] = __float2half(SCALE * (a.y + b.y));
    h[2] = __float2half(SCALE * (a.z + b.z));
    h[3] = __float2half(SCALE * (a.w + b.w));
    ((uint2*)g_Xf)[t] = *(const uint2*)h;
}

// ---------------- degree ----------------
__global__ __launch_bounds__(256) void deg_kernel(const int* __restrict__ eidx) {
    int e = blockIdx.x * 256 + threadIdx.x;
    if (e < EDGES) atomicAdd(&g_deg[__ldg(eidx + EDGES + e)], 1.0f);
}

// ---------------- all-weight split conversion (proj + both layers, one launch) --------
// layout: [proj][L0: rel0..7, self][L1: rel0..7, self], each 16384 elems
__global__ __launch_bounds__(256) void convert_w_all_kernel(const float* __restrict__ projW,
                                                            const float* __restrict__ selfW,
                                                            const float* __restrict__ relW) {
    int t = blockIdx.x * 256 + threadIdx.x;
    int f8 = t * 8;
    if (f8 >= NMAT * H * H) return;
    const float* src;
    if (f8 < H * H) {
        src = projW + f8;
    } else {
        int g = f8 - H * H;
        int l = g / ((RREL + 1) * H * H);
        int r = g % ((RREL + 1) * H * H);
        if (r < RREL * H * H) src = relW + (size_t)l * RREL * H * H + r;
        else src = selfW + (size_t)l * H * H + (r - RREL * H * H);
    }
    float4 a = *(const float4*)src;
    float4 b = *(const float4*)(src + 4);
    float v[8] = {a.x, a.y, a.z, a.w, b.x, b.y, b.z, b.w};
    __half hi[8], lo[8];
#pragma unroll
    for (int i = 0; i < 8; i++) split_h16(SCALE * v[i], hi[i], lo[i]);
    ((uint4*)g_Wh)[t] = *(const uint4*)hi;
    ((uint4*)g_Wl)[t] = *(const uint4*)lo;
}

// ---------------- proj GEMM (128x128x128, W resident, A streamed; verified R6 path) ---
// Xf = fp16 x64 of (E0 @ projW^T + projb), in-place over Xf (2-chain)
__global__ __launch_bounds__(256, 2) void mma_proj_kernel(const float* __restrict__ projb) {
    extern __shared__ __half sm[];
    const uint32_t sbase = smem_u32(sm);
    const int tid = threadIdx.x;
    const int m0 = blockIdx.x * 128;
    const __half* Ag = g_Xf + (size_t)m0 * H;

    {
        const __half* wsrc[2] = {g_Wh, g_Wl};
#pragma unroll
        for (int hl = 0; hl < 2; hl++) {
#pragma unroll
            for (int it = 0; it < 8; it++) {
                int i = tid + it * 256;
                int r = i >> 4;
                int c = i & 15;
                uint32_t dst = sbase + ((hl ? SW_L : SW_H) + r * PITCH_W + c * 8) * 2;
                cp_async16(dst, wsrc[hl] + r * H + c * 8);
            }
        }
#pragma unroll
        for (int it = 0; it < 2; it++) {
            int i = tid + it * 256;
            int r = i >> 2;
            int c = i & 3;
            uint32_t dst = sbase + (SA_OFF + r * PITCH_A + c * 8) * 2;
            cp_async16(dst, Ag + r * H + c * 8);
        }
        cp_commit();
        cp_wait0();
    }
    __syncthreads();

    const int wid = tid >> 5;
    const int lane = tid & 31;
    const int wm = wid >> 2;
    const int wn = wid & 3;

    float acc[4][4][4];
#pragma unroll
    for (int i = 0; i < 4; i++)
#pragma unroll
        for (int j = 0; j < 4; j++)
#pragma unroll
            for (int k = 0; k < 4; k++) acc[i][j][k] = 0.0f;

    const uint32_t lrow = lane & 15;
    const uint32_t lhalf = lane >> 4;
    const uint32_t aWh = sbase + (SW_H + (wn * 32 + lrow) * PITCH_W + lhalf * 8) * 2;
    const uint32_t aWl = sbase + (SW_L + (wn * 32 + lrow) * PITCH_W + lhalf * 8) * 2;
    const uint32_t aA0 = sbase + (SA_OFF + (wm * 64 + lrow) * PITCH_A + lhalf * 8) * 2;

#pragma unroll
    for (int kc = 0; kc < 4; kc++) {
        if (kc < 3) {
            int b = (kc + 1) & 1;
#pragma unroll
            for (int it = 0; it < 2; it++) {
                int i = tid + it * 256;
                int r = i >> 2;
                int c = i & 3;
                uint32_t dst = sbase + (SA_OFF + b * SA_SZ + r * PITCH_A + c * 8) * 2;
                cp_async16(dst, Ag + r * H + (kc + 1) * 32 + c * 8);
            }
            cp_commit();
        }
        const uint32_t aA = aA0 + (kc & 1) * (SA_SZ * 2);
#pragma unroll
        for (int kstep = 0; kstep < 2; kstep++) {
            const int ks = kc * 2 + kstep;
            const uint32_t wkoff = ks * 32;
            const uint32_t akoff = kstep * 32;
            uint32_t bh[2][4], bl[2][4];
#pragma unroll
            for (int bi = 0; bi < 2; bi++) {
                ldm_x4(bh[bi][0], bh[bi][1], bh[bi][2], bh[bi][3],
                       aWh + bi * (16 * PITCH_W * 2) + wkoff);
                ldm_x4(bl[bi][0], bl[bi][1], bl[bi][2], bl[bi][3],
                       aWl + bi * (16 * PITCH_W * 2) + wkoff);
            }
#pragma unroll
            for (int mi = 0; mi < 4; mi++) {
                uint32_t a[4];
                ldm_x4(a[0], a[1], a[2], a[3], aA + mi * (16 * PITCH_A * 2) + akoff);
#pragma unroll
                for (int bi = 0; bi < 2; bi++) {
                    mma16816(acc[mi][2 * bi + 0], a, bh[bi][0], bh[bi][2]);
                    mma16816(acc[mi][2 * bi + 1], a, bh[bi][1], bh[bi][3]);
                    mma16816(acc[mi][2 * bi + 0], a, bl[bi][0], bl[bi][2]);
                    mma16816(acc[mi][2 * bi + 1], a, bl[bi][1], bl[bi][3]);
                }
            }
        }
        if (kc < 3) {
            cp_wait0();
            __syncthreads();
        }
    }

    const int gID = lane >> 2;
    const int tig = lane & 3;
#pragma unroll
    for (int mi = 0; mi < 4; mi++) {
#pragma unroll
        for (int nt = 0; nt < 4; nt++) {
            int col = wn * 32 + nt * 8 + tig * 2;
            float b0 = __ldg(projb + col);
            float b1 = __ldg(projb + col + 1);
#pragma unroll
            for (int half = 0; half < 2; half++) {
                int row = m0 + wm * 64 + mi * 16 + gID + half * 8;
                float v0 = acc[mi][nt][2 * half + 0] * INV_SCALE2 + b0;
                float v1 = acc[mi][nt][2 * half + 1] * INV_SCALE2 + b1;
                __half2 hv;
                hv.x = __float2half(SCALE * v0);
                hv.y = __float2half(SCALE * v1);
                *(__half2*)(g_Xf + (size_t)row * H + col) = hv;
            }
        }
    }
}

// ---------------- fused layer kernel: A resident, 10 W chains streamed ----------------
// chains 0..7: Y[r] = A @ Wh[rel r]^T (fp16 out, /4096).
// chains 8,9:  Z = A @ (Wh+Wl)[self]^T /4096 + self_b (fp32 out).
__global__ __launch_bounds__(256, 2) void mma_layer_fused_kernel(const float* __restrict__ selfb,
                                                                 int l) {
    extern __shared__ __half sm[];
    const uint32_t sbase = smem_u32(sm);
    const int tid = threadIdx.x;
    const int m0 = blockIdx.x * 128;

    // W matrix list for this layer
    const size_t base = (size_t)(1 + l * (RREL + 1)) * H * H;
    const __half* wlist[10];
#pragma unroll
    for (int r = 0; r < RREL; r++) wlist[r] = g_Wh + base + (size_t)r * H * H;
    wlist[8] = g_Wh + base + (size_t)RREL * H * H;
    wlist[9] = g_Wl + base + (size_t)RREL * H * H;

    // prologue: A tile (resident) + W chain 0 into buf 0
    {
        const __half* Ag = g_Xf + (size_t)m0 * H;
#pragma unroll
        for (int it = 0; it < 8; it++) {
            int i = tid + it * 256;           // 0..2047, 16 chunks per row
            int r = i >> 4;
            int c = i & 15;
            cp_async16(sbase + (FA_OFF + r * PITCH_W + c * 8) * 2, Ag + r * H + c * 8);
        }
#pragma unroll
        for (int it = 0; it < 8; it++) {
            int i = tid + it * 256;
            int r = i >> 4;
            int c = i & 15;
            cp_async16(sbase + (FW0 + r * PITCH_W + c * 8) * 2, wlist[0] + r * H + c * 8);
        }
        cp_commit();
        cp_wait0();
    }
    __syncthreads();

    const int wid = tid >> 5;
    const int lane = tid & 31;
    const int wm = wid >> 2;       // 0..1 : 64-row block
    const int wn = wid & 3;        // 0..3 : 32-col block

    const uint32_t lrow = lane & 15;
    const uint32_t lhalf = lane >> 4;
    const uint32_t aA = sbase + (FA_OFF + (wm * 64 + lrow) * PITCH_W + lhalf * 8) * 2;
    const uint32_t aWb[2] = {
        sbase + (FW0 + (wn * 32 + lrow) * PITCH_W + lhalf * 8) * 2,
        sbase + (FW1 + (wn * 32 + lrow) * PITCH_W + lhalf * 8) * 2};

    const int gID = lane >> 2;
    const int tig = lane & 3;

    float acc[4][4][4];

#pragma unroll 1
    for (int ch = 0; ch < 10; ch++) {
        // prefetch next W into other buffer
        if (ch < 9) {
            const __half* wsrc = wlist[ch + 1];
            uint32_t wdst = sbase + ((((ch + 1) & 1) ? FW1 : FW0)) * 2;
#pragma unroll
            for (int it = 0; it < 8; it++) {
                int i = tid + it * 256;
                int r = i >> 4;
                int c = i & 15;
                cp_async16(wdst + (r * PITCH_W + c * 8) * 2, wsrc + r * H + c * 8);
            }
            cp_commit();
        }

        if (ch != 9) {
#pragma unroll
            for (int i = 0; i < 4; i++)
#pragma unroll
                for (int j = 0; j < 4; j++)
#pragma unroll
                    for (int k = 0; k < 4; k++) acc[i][j][k] = 0.0f;
        }

        const uint32_t aW = aWb[ch & 1];
#pragma unroll
        for (int ks = 0; ks < 8; ks++) {
            const uint32_t koff = ks * 32;    // 16 fp16 = 32 bytes
            uint32_t bh[2][4];
#pragma unroll
            for (int bi = 0; bi < 2; bi++) {
                ldm_x4(bh[bi][0], bh[bi][1], bh[bi][2], bh[bi][3],
                       aW + bi * (16 * PITCH_W * 2) + koff);
            }
#pragma unroll
            for (int mi = 0; mi < 4; mi++) {
                uint32_t a[4];
                ldm_x4(a[0], a[1], a[2], a[3], aA + mi * (16 * PITCH_W * 2) + koff);
#pragma unroll
                for (int bi = 0; bi < 2; bi++) {
                    mma16816(acc[mi][2 * bi + 0], a, bh[bi][0], bh[bi][2]);
                    mma16816(acc[mi][2 * bi + 1], a, bh[bi][1], bh[bi][3]);
                }
            }
        }

        // epilogue for relation chains (fp16 Y, unscaled)
        if (ch < 8) {
            __half* Yr = g_Y + (size_t)ch * NN * H;
#pragma unroll
            for (int mi = 0; mi < 4; mi++) {
#pragma unroll
                for (int nt = 0; nt < 4; nt++) {
                    int col = wn * 32 + nt * 8 + tig * 2;
#pragma unroll
                    for (int half = 0; half < 2; half++) {
                        int row = m0 + wm * 64 + mi * 16 + gID + half * 8;
                        __half2 hv;
                        hv.x = __float2half(acc[mi][nt][2 * half + 0] * INV_SCALE2);
                        hv.y = __float2half(acc[mi][nt][2 * half + 1] * INV_SCALE2);
                        *(__half2*)(Yr + (size_t)row * H + col) = hv;
                    }
                }
            }
        }

        if (ch < 9) {
            cp_wait0();
            __syncthreads();
        }
    }

    // self epilogue: fp32 + bias -> Z
#pragma unroll
    for (int mi = 0; mi < 4; mi++) {
#pragma unroll
        for (int nt = 0; nt < 4; nt++) {
            int col = wn * 32 + nt * 8 + tig * 2;
            float b0 = __ldg(selfb + col);
            float b1 = __ldg(selfb + col + 1);
#pragma unroll
            for (int half = 0; half < 2; half++) {
                int row = m0 + wm * 64 + mi * 16 + gID + half * 8;
                float2 fv = make_float2(acc[mi][nt][2 * half + 0] * INV_SCALE2 + b0,
                                        acc[mi][nt][2 * half + 1] * INV_SCALE2 + b1);
                *(float2*)(g_Z + (size_t)row * H + col) = fv;
            }
        }
    }
}

// ---------------- edge aggregation: Z[dst] += Y[type][src] / max(deg[dst],1) ----------
__global__ __launch_bounds__(256) void agg_kernel(const int* __restrict__ eidx,
                                                  const int* __restrict__ etype) {
    int e = (blockIdx.x * 256 + threadIdx.x) >> 5;
    int lane = threadIdx.x & 31;
    if (e >= EDGES) return;
    int src = __ldg(eidx + e);
    int dst = __ldg(eidx + EDGES + e);
    int r = __ldg(etype + e);
    float inv = 1.0f / fmaxf(__ldg(&g_deg[dst]), 1.0f);
    const uint2* yrow = (const uint2*)(g_Y + ((size_t)r * NN + src) * H);
    uint2 u = __ldg(yrow + lane);
    __half2 h0 = *(__half2*)&u.x;
    __half2 h1 = *(__half2*)&u.y;
    float2 f0 = __half22float2(h0);
    float2 f1 = __half22float2(h1);
    float4 v;
    v.x = f0.x * inv; v.y = f0.y * inv; v.z = f1.x * inv; v.w = f1.y * inv;
    atomicAdd(((float4*)(g_Z + (size_t)dst * H)) + lane, v);
}

// ---------------- relu passes ----------------
__global__ __launch_bounds__(256) void relu_f16_kernel() {
    int t = blockIdx.x * 256 + threadIdx.x;
    float4 z = ((const float4*)g_Z)[t];
    __half h[4];
    h[0] = __float2half(SCALE * fmaxf(z.x, 0.0f));
    h[1] = __float2half(SCALE * fmaxf(z.y, 0.0f));
    h[2] = __float2half(SCALE * fmaxf(z.z, 0.0f));
    h[3] = __float2half(SCALE * fmaxf(z.w, 0.0f));
    ((uint2*)g_Xf)[t] = *(const uint2*)h;
}

__global__ __launch_bounds__(256) void relu_out_kernel(float* __restrict__ out,
                                                       const int* __restrict__ mask) {
    int t = blockIdx.x * 256 + threadIdx.x;
    int node = t >> 5;
    float m = (float)__ldg(mask + node);
    float4 z = ((const float4*)g_Z)[t];
    float4 v;
    v.x = fmaxf(z.x, 0.0f) * m; v.y = fmaxf(z.y, 0.0f) * m;
    v.z = fmaxf(z.z, 0.0f) * m; v.w = fmaxf(z.w, 0.0f) * m;
    ((float4*)out)[t] = v;
}

// ---------------- launch ----------------
extern "C" void kernel_launch(void* const* d_in, const int* in_sizes, int n_in,
                              void* d_out, int out_size) {
    const int* cid     = (const int*)d_in[0];
    const int* kid     = (const int*)d_in[1];
    const int* mask    = (const int*)d_in[2];
    const int* eidx    = (const int*)d_in[3];
    const int* etype   = (const int*)d_in[4];
    const float* cemb  = (const float*)d_in[5];
    const float* kemb  = (const float*)d_in[6];
    const float* projW = (const float*)d_in[7];
    const float* projb = (const float*)d_in[8];
    const float* selfW = (const float*)d_in[9];
    const float* selfb = (const float*)d_in[10];
    const float* relW  = (const float*)d_in[11];
    float* out = (float*)d_out;

    const int proj_smem = SM_ELEMS * 2;      // 90112
    const int fused_smem = FSM_ELEMS * 2;    // 104448
    cudaFuncSetAttribute(mma_proj_kernel, cudaFuncAttributeMaxDynamicSharedMemorySize, proj_smem);
    cudaFuncSetAttribute(mma_layer_fused_kernel, cudaFuncAttributeMaxDynamicSharedMemorySize,
                         fused_smem);

    embed_kernel<<<(NN * 32) / 256, 256>>>(cid, kid, cemb, kemb);
    deg_kernel<<<EDGES / 256, 256>>>(eidx);
    convert_w_all_kernel<<<(NMAT * H * H / 8 + 255) / 256, 256>>>(projW, selfW, relW);
    mma_proj_kernel<<<NN / 128, 256, proj_smem>>>(projb);

    for (int l = 0; l < NLAYERS; l++) {
        mma_layer_fused_kernel<<<NN / 128, 256, fused_smem>>>(selfb + l * H, l);
        agg_kernel<<<EDGES / 8, 256>>>(eidx, etype);
        if (l == 0)
            relu_f16_kernel<<<(NN * 32) / 256, 256>>>();
        else
            relu_out_kernel<<<(NN * 32) / 256, 256>>>(out, mask);
    }
}